// round 12
// baseline (speedup 1.0000x reference)
#include <cuda_runtime.h>
#include <cuda_fp16.h>

// DWHT (buggy torch in-place semantics) + channel shuffle, fully fused.
// x: (64, 256, 28, 28) f32  ->  out: (64, 512, 28, 28) f32
//
// 8 passes = (F o F)^4; G = F o F maps each aligned 16-channel chunk to a
// fixed signed output set. Channel shuffle (groups=8) folded into affine
// stage-4 addresses.
//
// Round-11 = R9 (best: fp16 smem storage / fp32 compute, zero-pad sparsity,
// CSE butterfly, 32KB static smem, 3 blocks/SM) +
//   * QUAD-packed half layout: sidx(c,p) = (c/4)*128 + 4p + (c&3) (halves)
//     -> chunk reads are 4x LDS.64, A/C/G4 stores STS.64; conflict-free,
//     wavefront-neutral, ~32% fewer LSU instructions per exchange.
//   * Affine-folded global store addressing (no runtime shuffle math).

#define NPIX 32

struct GOut {
    float4 Al;              // -> 4*jl + q
    float2 Bl, Dl, Gl;      // -> 128+2jl, 256+2jl, 384+2jl
    float  El;              // -> 320+jl
    float4 Ah, Ch, G4h;     // -> 4*jh+q, 128+4jh+q, 384+4jh+q
    float2 Bh, Dh, G2h, Fh; // -> 128+2jh, 256+2jh, 384+2jh, 320+2jh
    float  Eh;              // -> 320+jh
};

// CSE'd butterfly: s=pair sums, d=pair diffs, t/u=second-level sums/diffs.
__device__ __forceinline__ GOut compute_G(const float wl[16], const float wh[16]) {
    GOut o;
    float s[8], t[4], u[4];
#pragma unroll
    for (int i = 0; i < 8; i++) s[i] = wl[2*i] + wl[2*i+1];
#pragma unroll
    for (int q = 0; q < 4; q++) { t[q] = s[2*q] + s[2*q+1]; u[q] = s[2*q] - s[2*q+1]; }
    o.Al = make_float4(t[0], t[1], t[2], t[3]);
    o.Bl = make_float2(u[0] + u[1], u[2] + u[3]);
    o.Dl = make_float2(t[0] - t[1], t[2] - t[3]);
    o.Gl = make_float2(u[0] - u[1], u[2] - u[3]);
    o.El = o.Bl.x - o.Bl.y;

    float d[8];
#pragma unroll
    for (int i = 0; i < 8; i++) { s[i] = wh[2*i] + wh[2*i+1]; d[i] = wh[2*i] - wh[2*i+1]; }
#pragma unroll
    for (int q = 0; q < 4; q++) { t[q] = s[2*q] + s[2*q+1]; u[q] = s[2*q] - s[2*q+1]; }
    o.Ah  = make_float4(t[0], t[1], t[2], t[3]);
    o.Bh  = make_float2(u[0] + u[1], u[2] + u[3]);
    o.Dh  = make_float2(t[0] - t[1], t[2] - t[3]);
    o.G2h = make_float2(u[0] - u[1], u[2] - u[3]);
    o.Eh  = o.Bh.x - o.Bh.y;
    float c0 = d[0]+d[1], c1 = d[2]+d[3], c2 = d[4]+d[5], c3 = d[6]+d[7];
    o.Ch  = make_float4(c0, c1, c2, c3);
    o.G4h = make_float4(d[0]-d[1], d[2]-d[3], d[4]-d[5], d[6]-d[7]);
    o.Fh  = make_float2(c0 - c1, c2 - c3);
    return o;
}

__device__ __forceinline__ void zero16(float w[16]) {
#pragma unroll
    for (int m = 0; m < 16; m++) w[m] = 0.0f;
}

// Quad-packed half layout, addresses in HALVES:
//   sidx(c,p) = (c>>2)*128 + 4*p + (c&3)
// Read one 16-channel chunk as 4 conflict-free LDS.64 (uint2 = 4 halves).
__device__ __forceinline__ void load_chunk(const __half* __restrict__ s, int chunk,
                                           int p, float w[16]) {
#pragma unroll
    for (int i = 0; i < 4; i++) {
        uint2 raw = *(const uint2*)(s + (4 * chunk + i) * 128 + 4 * p);
        float2 a = __half22float2(*(__half2*)&raw.x);
        float2 b = __half22float2(*(__half2*)&raw.y);
        w[4*i+0] = a.x; w[4*i+1] = a.y; w[4*i+2] = b.x; w[4*i+3] = b.y;
    }
}

// c % 4 == 0: one STS.64 (4 channels)
__device__ __forceinline__ void sts4(__half* __restrict__ s, int c, int p,
                                     float4 v) {
    __half2 lo = __floats2half2_rn(v.x, v.y);
    __half2 hi = __floats2half2_rn(v.z, v.w);
    uint2 raw;
    raw.x = *(unsigned*)&lo; raw.y = *(unsigned*)&hi;
    *(uint2*)(s + (c >> 2) * 128 + 4 * p) = raw;
}
// c % 2 == 0: STS.32 (2 channels)
__device__ __forceinline__ void sts2(__half* __restrict__ s, int c, int p,
                                     float2 v) {
    *(__half2*)(s + (c >> 2) * 128 + 4 * p + (c & 3)) = __floats2half2_rn(v.x, v.y);
}
// scalar: STS.16
__device__ __forceinline__ void sts1(__half* __restrict__ s, int c, int p, float v) {
    s[(c >> 2) * 128 + 4 * p + (c & 3)] = __float2half_rn(v);
}

__device__ __forceinline__ void store_G(__half* __restrict__ s, int jl, int p,
                                        const GOut& o, bool skipAl, bool skipH4) {
    const int jh = jl + 16;
    if (!skipAl) sts4(s, 4*jl, p, o.Al);          // dead chunks 1,3 when skipped
    sts2(s, 128 + 2*jl, p, o.Bl);
    sts2(s, 256 + 2*jl, p, o.Dl);
    sts2(s, 384 + 2*jl, p, o.Gl);
    sts1(s, 320 + jl, p, o.El);
    if (!skipH4) {                                 // dead chunks 7,15,31
        sts4(s, 4*jh,       p, o.Ah);
        sts4(s, 128 + 4*jh, p, o.Ch);
        sts4(s, 384 + 4*jh, p, o.G4h);
    }
    sts2(s, 128 + 2*jh, p, o.Bh);
    sts2(s, 256 + 2*jh, p, o.Dh);
    sts2(s, 384 + 2*jh, p, o.G2h);
    sts2(s, 320 + 2*jh, p, o.Fh);
    sts1(s, 320 + jh, p, o.Eh);
}

__global__ __launch_bounds__(512, 3)
void dwht_kernel(const float* __restrict__ x, float* __restrict__ out) {
    __shared__ __half s[128 * 128];     // 512 ch quad-packed x 32 px = 32 KB

    const int tid = threadIdx.x;
    const int p   = tid & (NPIX - 1);   // pixel lane within warp [0,32)
    const int jl  = tid >> 5;           // chunk pair id = warp id [0,16)
    const int jh  = jl + 16;

    const int b    = blockIdx.x / 25;
    const int hw   = (blockIdx.x % 25) * NPIX + p;
    const bool valid = (hw < 784);
    const float* xp = x   + (size_t)b * (256 * 784) + hw;
    float*       op = out + (size_t)b * (512 * 784) + hw;

    float wl[16], wh[16];

    // ---- stage 1: global load; high 256 channels are the zero pad ----
#pragma unroll
    for (int m = 0; m < 16; m++) wl[m] = valid ? xp[(16 * jl + m) * 784] : 0.0f;
    zero16(wh);
    {
        GOut o = compute_G(wl, wh);     // high outputs fold to 0 and are DCE'd
        sts4(s, 4*jl, p, o.Al);
        sts2(s, 128 + 2*jl, p, o.Bl);
        sts2(s, 256 + 2*jl, p, o.Dl);
        sts2(s, 384 + 2*jl, p, o.Gl);
        sts1(s, 320 + jl, p, o.El);
    }
    __syncthreads();

    // ---- stage 2: nonzero input chunks {0,1,2,3,8,9,16,17,20,24,25} ----
    {
        const bool rl = (jl <= 3) | (jl == 8) | (jl == 9);
        const bool rh = (jl <= 1) | (jl == 4) | (jl == 8) | (jl == 9);
        if (rl) load_chunk(s, jl, p, wl); else zero16(wl);
        if (rh) load_chunk(s, jh, p, wh); else zero16(wh);
        GOut o = compute_G(wl, wh);
        __syncthreads();                 // all reads done before overwrite
        // outputs landing in chunks {1,3,7,15,31} are exact zeros: skip stores
        const bool skipAl = ((jl >= 4) & (jl <= 7)) | (jl >= 12);
        const bool skipH4 = (jl >= 12);
        store_G(s, jl, p, o, skipAl, skipH4);
        __syncthreads();
    }

    // ---- stage 3: chunks {1,3,7,15,31} are identically zero: skip reads ----
    {
        const bool rl = !((jl == 1) | (jl == 3) | (jl == 7) | (jl == 15));
        const bool rh = (jl != 15);
        if (rl) load_chunk(s, jl, p, wl); else zero16(wl);
        if (rh) load_chunk(s, jh, p, wh); else zero16(wh);
        GOut o = compute_G(wl, wh);
        __syncthreads();
        store_G(s, jl, p, o, false, false);
        __syncthreads();
    }

    // ---- stage 4: smem -> registers -> shuffled global store ----
    load_chunk(s, jl, p, wl);
    load_chunk(s, jh, p, wh);
    {
        GOut o = compute_G(wl, wh);
        if (valid) {
            // Shuffle c=((idx&63)<<3)|(idx>>6) solved per family:
            //   A:32jl+8q  Ah:+1  Ch:+3  G4h:+7     (base q32)
            //   Bl/Dl/Gl: 16jl+8r+{2,4,6}           (base q16)
            //   Bh/Dh/Fh/G2h: 256+16jl+8r+{2,4,5,6} (base q16h)
            //   El: 8jl+5   Eh: 8jl+133             (base qE)
            float* q32  = op + (size_t)(32 * jl) * 784;
            float* q16  = op + (size_t)(16 * jl) * 784;
            float* q16h = q16 + (size_t)256 * 784;
            float* qE   = op + (size_t)(8 * jl) * 784;
            q32[(size_t)( 0*8+0)*784] = o.Al.x;
            q32[(size_t)( 1*8+0)*784] = o.Al.y;
            q32[(size_t)( 2*8+0)*784] = o.Al.z;
            q32[(size_t)( 3*8+0)*784] = o.Al.w;
            q32[(size_t)( 0*8+1)*784] = o.Ah.x;
            q32[(size_t)( 1*8+1)*784] = o.Ah.y;
            q32[(size_t)( 2*8+1)*784] = o.Ah.z;
            q32[(size_t)( 3*8+1)*784] = o.Ah.w;
            q32[(size_t)( 0*8+3)*784] = o.Ch.x;
            q32[(size_t)( 1*8+3)*784] = o.Ch.y;
            q32[(size_t)( 2*8+3)*784] = o.Ch.z;
            q32[(size_t)( 3*8+3)*784] = o.Ch.w;
            q32[(size_t)( 0*8+7)*784] = o.G4h.x;
            q32[(size_t)( 1*8+7)*784] = o.G4h.y;
            q32[(size_t)( 2*8+7)*784] = o.G4h.z;
            q32[(size_t)( 3*8+7)*784] = o.G4h.w;
            q16[(size_t)(0*8+2)*784] = o.Bl.x;
            q16[(size_t)(1*8+2)*784] = o.Bl.y;
            q16[(size_t)(0*8+4)*784] = o.Dl.x;
            q16[(size_t)(1*8+4)*784] = o.Dl.y;
            q16[(size_t)(0*8+6)*784] = o.Gl.x;
            q16[(size_t)(1*8+6)*784] = o.Gl.y;
            q16h[(size_t)(0*8+2)*784] = o.Bh.x;
            q16h[(size_t)(1*8+2)*784] = o.Bh.y;
            q16h[(size_t)(0*8+4)*784] = o.Dh.x;
            q16h[(size_t)(1*8+4)*784] = o.Dh.y;
            q16h[(size_t)(0*8+5)*784] = o.Fh.x;
            q16h[(size_t)(1*8+5)*784] = o.Fh.y;
            q16h[(size_t)(0*8+6)*784] = o.G2h.x;
            q16h[(size_t)(1*8+6)*784] = o.G2h.y;
            qE[(size_t)  5*784] = o.El;
            qE[(size_t)133*784] = o.Eh;
        }
    }
}

extern "C" void kernel_launch(void* const* d_in, const int* in_sizes, int n_in,
                              void* d_out, int out_size) {
    const float* x = (const float*)d_in[0];
    float* out = (float*)d_out;
    // 64 images * 25 pixel-tiles of 32 (last tile predicated: 784 = 24*32+16)
    dwht_kernel<<<64 * 25, 512>>>(x, out);
}